// round 3
// baseline (speedup 1.0000x reference)
#include <cuda_runtime.h>
#include <cuda_bf16.h>
#include <math.h>

// Problem constants: B=4, H=16, S=2048, D=64
#define Bb 4
#define Hh 16
#define Ss 2048
#define Dd 64
#define BH (Bb*Hh)

static const long long OUT_ELEMS   = (long long)Bb * Hh * Ss * Dd;   // 8,388,608
static const long long SCORE_ELEMS = (long long)Bb * Hh * Ss * Ss;   // 268,435,456

#define SCALE 0.125f   // 1/sqrt(64)

// ---------------------------------------------------------------------------
// Kernel 1: scores[z, qi, kj] = mask ? (Q.K^T)*scale : 1e-12
// 64x64 output tile per block, K-dim = 64 (full), 256 threads, 4x4 micro-tile.
// ---------------------------------------------------------------------------
__global__ __launch_bounds__(256) void scores_kernel(
    const float4* __restrict__ Q4, const float4* __restrict__ K4,
    const int* __restrict__ mask, float* __restrict__ score)
{
    const int nTile = blockIdx.x;   // kj tile
    const int mTile = blockIdx.y;   // qi tile
    const int z     = blockIdx.z;   // b*H + h
    const int bidx  = z >> 4;       // H = 16

    __shared__ float Qs[64][65];
    __shared__ float Ks[64][65];

    const int t = threadIdx.x;

    // Load Q tile [64 rows x 64 cols] and K tile [64 rows x 64 cols] (row-major)
    const float4* Qbase = Q4 + ((size_t)z * Ss + (size_t)mTile * 64) * (Dd / 4);
    const float4* Kbase = K4 + ((size_t)z * Ss + (size_t)nTile * 64) * (Dd / 4);
#pragma unroll
    for (int it = 0; it < 4; ++it) {
        int lin = t + it * 256;          // 0..1023 float4s
        int m   = lin >> 4;              // row 0..63
        int kg  = lin & 15;              // float4 group 0..15
        float4 v = Qbase[m * 16 + kg];
        Qs[m][kg * 4 + 0] = v.x; Qs[m][kg * 4 + 1] = v.y;
        Qs[m][kg * 4 + 2] = v.z; Qs[m][kg * 4 + 3] = v.w;
        float4 w = Kbase[m * 16 + kg];
        Ks[m][kg * 4 + 0] = w.x; Ks[m][kg * 4 + 1] = w.y;
        Ks[m][kg * 4 + 2] = w.z; Ks[m][kg * 4 + 3] = w.w;
    }
    __syncthreads();

    const int tx = t & 15;   // n position (16)
    const int ty = t >> 4;   // m position (16)

    float acc[4][4];
#pragma unroll
    for (int i = 0; i < 4; ++i)
#pragma unroll
        for (int j = 0; j < 4; ++j) acc[i][j] = 0.0f;

#pragma unroll 16
    for (int kk = 0; kk < 64; ++kk) {
        float a0 = Qs[ty * 4 + 0][kk];
        float a1 = Qs[ty * 4 + 1][kk];
        float a2 = Qs[ty * 4 + 2][kk];
        float a3 = Qs[ty * 4 + 3][kk];
        float b0 = Ks[tx * 4 + 0][kk];
        float b1 = Ks[tx * 4 + 1][kk];
        float b2 = Ks[tx * 4 + 2][kk];
        float b3 = Ks[tx * 4 + 3][kk];
        acc[0][0] += a0 * b0; acc[0][1] += a0 * b1; acc[0][2] += a0 * b2; acc[0][3] += a0 * b3;
        acc[1][0] += a1 * b0; acc[1][1] += a1 * b1; acc[1][2] += a1 * b2; acc[1][3] += a1 * b3;
        acc[2][0] += a2 * b0; acc[2][1] += a2 * b1; acc[2][2] += a2 * b2; acc[2][3] += a2 * b3;
        acc[3][0] += a3 * b0; acc[3][1] += a3 * b1; acc[3][2] += a3 * b2; acc[3][3] += a3 * b3;
    }

    // Epilogue: scale, mask, store (mask shape [B,1,S,S], shared across heads)
    const int qi0 = mTile * 64 + ty * 4;
    const int kj0 = nTile * 64 + tx * 4;
    const int4*  mrow = (const int4*)(mask + (size_t)bidx * Ss * Ss);
    float*       srow = score + (size_t)z * Ss * Ss;

#pragma unroll
    for (int i = 0; i < 4; ++i) {
        int qi = qi0 + i;
        int4 mk = mrow[((size_t)qi * Ss + kj0) >> 2];
        float4 s;
        s.x = (mk.x == 0) ? 1e-12f : acc[i][0] * SCALE;
        s.y = (mk.y == 0) ? 1e-12f : acc[i][1] * SCALE;
        s.z = (mk.z == 0) ? 1e-12f : acc[i][2] * SCALE;
        s.w = (mk.w == 0) ? 1e-12f : acc[i][3] * SCALE;
        *(float4*)(srow + (size_t)qi * Ss + kj0) = s;
    }
}

// ---------------------------------------------------------------------------
// Kernel 2: row softmax in-place. One block (256 thr) per row of 2048.
// Entire row lives in registers: exactly 1 read + 1 write of the score buffer.
// ---------------------------------------------------------------------------
__global__ __launch_bounds__(256) void softmax_kernel(float* __restrict__ score)
{
    const long long row = blockIdx.x;          // 0 .. BH*S-1
    float4* p = (float4*)(score + row * (long long)Ss);   // 512 float4s

    const int t = threadIdx.x;
    float4 v0 = p[t];
    float4 v1 = p[t + 256];

    // --- max reduce ---
    float mx = fmaxf(fmaxf(fmaxf(v0.x, v0.y), fmaxf(v0.z, v0.w)),
                     fmaxf(fmaxf(v1.x, v1.y), fmaxf(v1.z, v1.w)));
#pragma unroll
    for (int off = 16; off > 0; off >>= 1)
        mx = fmaxf(mx, __shfl_xor_sync(0xFFFFFFFFu, mx, off));

    __shared__ float red[8];
    const int wid = t >> 5, lid = t & 31;
    if (lid == 0) red[wid] = mx;
    __syncthreads();
    if (wid == 0) {
        float m = (lid < 8) ? red[lid] : -3.402823466e38f;
#pragma unroll
        for (int off = 4; off > 0; off >>= 1)
            m = fmaxf(m, __shfl_xor_sync(0xFFFFFFFFu, m, off));
        if (lid == 0) red[0] = m;
    }
    __syncthreads();
    mx = red[0];

    // --- exp + sum ---
    v0.x = __expf(v0.x - mx); v0.y = __expf(v0.y - mx);
    v0.z = __expf(v0.z - mx); v0.w = __expf(v0.w - mx);
    v1.x = __expf(v1.x - mx); v1.y = __expf(v1.y - mx);
    v1.z = __expf(v1.z - mx); v1.w = __expf(v1.w - mx);

    float sm = (v0.x + v0.y) + (v0.z + v0.w) + (v1.x + v1.y) + (v1.z + v1.w);
#pragma unroll
    for (int off = 16; off > 0; off >>= 1)
        sm += __shfl_xor_sync(0xFFFFFFFFu, sm, off);

    __shared__ float red2[8];
    if (lid == 0) red2[wid] = sm;
    __syncthreads();
    if (wid == 0) {
        float s2 = (lid < 8) ? red2[lid] : 0.0f;
#pragma unroll
        for (int off = 4; off > 0; off >>= 1)
            s2 += __shfl_xor_sync(0xFFFFFFFFu, s2, off);
        if (lid == 0) red2[0] = s2;
    }
    __syncthreads();
    const float inv = 1.0f / red2[0];

    v0.x *= inv; v0.y *= inv; v0.z *= inv; v0.w *= inv;
    v1.x *= inv; v1.y *= inv; v1.z *= inv; v1.w *= inv;
    p[t] = v0;
    p[t + 256] = v1;
}

// ---------------------------------------------------------------------------
// Kernel 3: out[z, qi, d] = sum_kj P[z, qi, kj] * V[z, kj, d]
// 64x64 output tile (m x D) per block, K loop over 2048 in chunks of 64.
// ---------------------------------------------------------------------------
__global__ __launch_bounds__(256) void av_kernel(
    const float* __restrict__ P, const float4* __restrict__ V4,
    float* __restrict__ out)
{
    const int mTile = blockIdx.x;   // qi tile (32)
    const int z     = blockIdx.z;   // bh (64)

    __shared__ float Ps[64][65];
    __shared__ float Vs[64][65];

    const int t  = threadIdx.x;
    const int tx = t & 15;
    const int ty = t >> 4;

    float acc[4][4];
#pragma unroll
    for (int i = 0; i < 4; ++i)
#pragma unroll
        for (int j = 0; j < 4; ++j) acc[i][j] = 0.0f;

    const float*  Pbase = P + ((size_t)z * Ss + (size_t)mTile * 64) * Ss;
    const float4* Vbase = V4 + (size_t)z * Ss * (Dd / 4);

    for (int kc = 0; kc < Ss / 64; ++kc) {
        // Load P chunk: rows 0..63, cols kc*64 .. kc*64+63
#pragma unroll
        for (int it = 0; it < 4; ++it) {
            int lin = t + it * 256;
            int m   = lin >> 4;
            int kg  = lin & 15;
            float4 v = *(const float4*)(Pbase + (size_t)m * Ss + kc * 64 + kg * 4);
            Ps[m][kg * 4 + 0] = v.x; Ps[m][kg * 4 + 1] = v.y;
            Ps[m][kg * 4 + 2] = v.z; Ps[m][kg * 4 + 3] = v.w;
            // Load V chunk: rows kc*64+r, cols 0..63
            float4 w = Vbase[(size_t)(kc * 64 + m) * 16 + kg];
            Vs[m][kg * 4 + 0] = w.x; Vs[m][kg * 4 + 1] = w.y;
            Vs[m][kg * 4 + 2] = w.z; Vs[m][kg * 4 + 3] = w.w;
        }
        __syncthreads();

#pragma unroll 16
        for (int kk = 0; kk < 64; ++kk) {
            float a0 = Ps[ty * 4 + 0][kk];
            float a1 = Ps[ty * 4 + 1][kk];
            float a2 = Ps[ty * 4 + 2][kk];
            float a3 = Ps[ty * 4 + 3][kk];
            float b0 = Vs[kk][tx * 4 + 0];
            float b1 = Vs[kk][tx * 4 + 1];
            float b2 = Vs[kk][tx * 4 + 2];
            float b3 = Vs[kk][tx * 4 + 3];
            acc[0][0] += a0 * b0; acc[0][1] += a0 * b1; acc[0][2] += a0 * b2; acc[0][3] += a0 * b3;
            acc[1][0] += a1 * b0; acc[1][1] += a1 * b1; acc[1][2] += a1 * b2; acc[1][3] += a1 * b3;
            acc[2][0] += a2 * b0; acc[2][1] += a2 * b1; acc[2][2] += a2 * b2; acc[2][3] += a2 * b3;
            acc[3][0] += a3 * b0; acc[3][1] += a3 * b1; acc[3][2] += a3 * b2; acc[3][3] += a3 * b3;
        }
        __syncthreads();
    }

    const int qi0 = mTile * 64 + ty * 4;
    const int dj0 = tx * 4;
#pragma unroll
    for (int i = 0; i < 4; ++i) {
        float4 o;
        o.x = acc[i][0]; o.y = acc[i][1]; o.z = acc[i][2]; o.w = acc[i][3];
        *(float4*)(out + ((size_t)z * Ss + qi0 + i) * Dd + dj0) = o;
    }
}

// ---------------------------------------------------------------------------
extern "C" void kernel_launch(void* const* d_in, const int* in_sizes, int n_in,
                              void* d_out, int out_size)
{
    const float* q    = (const float*)d_in[0];
    const float* k    = (const float*)d_in[1];
    const float* v    = (const float*)d_in[2];
    const int*   mask = (const int*)d_in[3];

    float* out   = (float*)d_out;
    float* score = out + OUT_ELEMS;   // tuple output: (output, score) concatenated

    // K1: scores = mask ? QK^T/8 : 1e-12
    {
        dim3 grid(Ss / 64, Ss / 64, BH);
        scores_kernel<<<grid, 256>>>((const float4*)q, (const float4*)k, mask, score);
    }
    // K2: in-place row softmax
    {
        softmax_kernel<<<(unsigned)(BH * Ss), 256>>>(score);
    }
    // K3: out = P @ V
    {
        dim3 grid(Ss / 64, 1, BH);
        av_kernel<<<grid, 256>>>(score, (const float4*)v, out);
    }
}

// round 7
// speedup vs baseline: 1.7294x; 1.7294x over previous
#include <cuda_runtime.h>
#include <cuda_fp16.h>
#include <cstdint>
#include <math.h>

// Problem constants: B=4, H=16, S=2048, D=64
#define Bb 4
#define Hh 16
#define Ss 2048
#define Dd 64
#define BH (Bb*Hh)
#define SCALE 0.125f

static const long long OUT_ELEMS = (long long)Bb * Hh * Ss * Dd;   // 8,388,608

// Per-row softmax stats (written by K1, read by K2)
__device__ float g_rowM[BH * Ss];
__device__ float g_rowL[BH * Ss];

// ===========================================================================
// helpers
// ===========================================================================
__device__ __forceinline__ uint32_t smem_u32(const void* p) {
    uint32_t a;
    asm("{ .reg .u64 t; cvta.to.shared.u64 t, %1; cvt.u32.u64 %0, t; }"
        : "=r"(a) : "l"(p));
    return a;
}

__device__ __forceinline__ void ldsm_x4(uint32_t addr, uint32_t& r0, uint32_t& r1,
                                        uint32_t& r2, uint32_t& r3) {
    asm volatile("ldmatrix.sync.aligned.m8n8.x4.shared.b16 {%0,%1,%2,%3}, [%4];"
                 : "=r"(r0), "=r"(r1), "=r"(r2), "=r"(r3) : "r"(addr));
}

__device__ __forceinline__ void ldsm_x4_t(uint32_t addr, uint32_t& r0, uint32_t& r1,
                                          uint32_t& r2, uint32_t& r3) {
    asm volatile("ldmatrix.sync.aligned.m8n8.x4.trans.shared.b16 {%0,%1,%2,%3}, [%4];"
                 : "=r"(r0), "=r"(r1), "=r"(r2), "=r"(r3) : "r"(addr));
}

__device__ __forceinline__ void mma16816(float* c, uint32_t a0, uint32_t a1,
                                         uint32_t a2, uint32_t a3,
                                         uint32_t b0, uint32_t b1) {
    asm volatile("mma.sync.aligned.m16n8k16.row.col.f32.f16.f16.f32 "
                 "{%0,%1,%2,%3}, {%4,%5,%6,%7}, {%8,%9}, {%0,%1,%2,%3};"
                 : "+f"(c[0]), "+f"(c[1]), "+f"(c[2]), "+f"(c[3])
                 : "r"(a0), "r"(a1), "r"(a2), "r"(a3), "r"(b0), "r"(b1));
}

// pack two floats to fp16x2 (hi), also produce residual fp16x2 (lo)
__device__ __forceinline__ uint32_t pack_hilo(float x, float y, uint32_t& lo) {
    __half hx = __float2half_rn(x), hy = __float2half_rn(y);
    float rx = x - __half2float(hx);
    float ry = y - __half2float(hy);
    lo = (uint32_t)__half_as_ushort(__float2half_rn(rx)) |
         ((uint32_t)__half_as_ushort(__float2half_rn(ry)) << 16);
    return (uint32_t)__half_as_ushort(hx) | ((uint32_t)__half_as_ushort(hy) << 16);
}
__device__ __forceinline__ uint32_t pack_h(float x, float y) {
    return (uint32_t)__half_as_ushort(__float2half_rn(x)) |
           ((uint32_t)__half_as_ushort(__float2half_rn(y)) << 16);
}

// ===========================================================================
// Kernel 1: raw masked scores + per-row (max, sumexp) stats
// grid (z=BH, qt=16), block 256 = 8 warps. Block tile: 128 q-rows x 2048 cols.
// Warp w owns rows 16w..16w+15. Loops 16 k-tiles of 128 cols.
// smem: Qhi/Qlo [128 x 64] fp16 (row pitch 144B), Khi [128 x 64] fp16.
// ===========================================================================
#define S1_QHI 0
#define S1_QLO 18432
#define S1_KHI 36864
#define S1_SIZE 55296

__global__ __launch_bounds__(256, 2) void scores_kernel(
    const float4* __restrict__ Q4, const float4* __restrict__ K4,
    const int* __restrict__ mask, float* __restrict__ score)
{
    extern __shared__ char sm[];
    const uint32_t smb = smem_u32(sm);
    const int t = threadIdx.x, lane = t & 31, w = t >> 5;
    const int z = blockIdx.x, qt = blockIdx.y, b = z >> 4;

    // ---- load Q tile [128 x 64] fp32 -> fp16 hi/lo ----
    {
        const int row = t >> 1, ch = t & 1;
        const float4* g = Q4 + ((size_t)z * Ss + (size_t)qt * 128 + row) * 16 + ch * 8;
        char* dh = sm + S1_QHI + row * 144 + ch * 64;
        char* dl = sm + S1_QLO + row * 144 + ch * 64;
#pragma unroll
        for (int c = 0; c < 4; ++c) {
            float4 a = g[2 * c], bq = g[2 * c + 1];
            uint32_t l0, l1, l2, l3;
            uint4 hh;
            hh.x = pack_hilo(a.x, a.y, l0);
            hh.y = pack_hilo(a.z, a.w, l1);
            hh.z = pack_hilo(bq.x, bq.y, l2);
            hh.w = pack_hilo(bq.z, bq.w, l3);
            *reinterpret_cast<uint4*>(dh + c * 16) = hh;
            *reinterpret_cast<uint4*>(dl + c * 16) = make_uint4(l0, l1, l2, l3);
        }
    }

    const int tig = lane & 3;
    const int r0 = qt * 128 + w * 16 + (lane >> 2);   // global q-row (lane-quad owned)
    const int* mrow0 = mask + (size_t)b * Ss * Ss + (size_t)r0 * Ss;
    const int* mrow1 = mrow0 + 8 * Ss;
    float* srow0 = score + (size_t)z * Ss * Ss + (size_t)r0 * Ss;
    float* srow1 = srow0 + 8 * Ss;

    float acc[64];
    float m0 = -INFINITY, m1 = -INFINITY, l0s = 0.0f, l1s = 0.0f;

    for (int kt = 0; kt < 16; ++kt) {
        __syncthreads();   // protect Khi (and on kt=0, Q tile) before overwrite/use
        // ---- load K tile [128 x 64] fp32 -> fp16 (hi only) ----
        {
            const int row = t >> 1, ch = t & 1;
            const float4* g = K4 + ((size_t)z * Ss + (size_t)kt * 128 + row) * 16 + ch * 8;
            char* d = sm + S1_KHI + row * 144 + ch * 64;
#pragma unroll
            for (int c = 0; c < 4; ++c) {
                float4 a = g[2 * c], bv = g[2 * c + 1];
                uint4 hh;
                hh.x = pack_h(a.x, a.y);  hh.y = pack_h(a.z, a.w);
                hh.z = pack_h(bv.x, bv.y); hh.w = pack_h(bv.z, bv.w);
                *reinterpret_cast<uint4*>(d + c * 16) = hh;
            }
        }
        __syncthreads();

#pragma unroll
        for (int i = 0; i < 64; ++i) acc[i] = 0.0f;

        // ---- MMA: S tile [16 x 128] per warp, K-dim 64 (4 steps), A=hi+lo ----
#pragma unroll
        for (int ks = 0; ks < 4; ++ks) {
            const uint32_t aoff = (uint32_t)((w * 16 + (lane & 15)) * 144 +
                                             ks * 32 + (lane >> 4) * 16);
            uint32_t ah0, ah1, ah2, ah3, al0, al1, al2, al3;
            ldsm_x4(smb + S1_QHI + aoff, ah0, ah1, ah2, ah3);
            ldsm_x4(smb + S1_QLO + aoff, al0, al1, al2, al3);
#pragma unroll
            for (int nf2 = 0; nf2 < 8; ++nf2) {
                const int n0 = nf2 * 16;
                const uint32_t baddr = smb + S1_KHI +
                    (uint32_t)((n0 + (lane >> 4) * 8 + (lane & 7)) * 144 +
                               (ks * 16 + ((lane >> 3) & 1) * 8) * 2);
                uint32_t b0, b1, b2, b3;
                ldsm_x4(baddr, b0, b1, b2, b3);
                mma16816(acc + nf2 * 8,     ah0, ah1, ah2, ah3, b0, b1);
                mma16816(acc + nf2 * 8,     al0, al1, al2, al3, b0, b1);
                mma16816(acc + nf2 * 8 + 4, ah0, ah1, ah2, ah3, b2, b3);
                mma16816(acc + nf2 * 8 + 4, al0, al1, al2, al3, b2, b3);
            }
        }

        // ---- epilogue: mask+scale, store raw score, online stats ----
        float cmax0 = -INFINITY, cmax1 = -INFINITY;
        const int cb = kt * 128;
#pragma unroll
        for (int nf = 0; nf < 16; ++nf) {
            const int c = cb + nf * 8 + tig * 2;
            int2 mk0 = *reinterpret_cast<const int2*>(mrow0 + c);
            int2 mk1 = *reinterpret_cast<const int2*>(mrow1 + c);
            float* a = acc + nf * 4;
            float s0 = (mk0.x == 0) ? 1e-12f : a[0] * SCALE;
            float s1 = (mk0.y == 0) ? 1e-12f : a[1] * SCALE;
            float s2 = (mk1.x == 0) ? 1e-12f : a[2] * SCALE;
            float s3 = (mk1.y == 0) ? 1e-12f : a[3] * SCALE;
            float2 w0; w0.x = s0; w0.y = s1;
            float2 w1; w1.x = s2; w1.y = s3;
            *reinterpret_cast<float2*>(srow0 + c) = w0;
            *reinterpret_cast<float2*>(srow1 + c) = w1;
            a[0] = s0; a[1] = s1; a[2] = s2; a[3] = s3;
            cmax0 = fmaxf(cmax0, fmaxf(s0, s1));
            cmax1 = fmaxf(cmax1, fmaxf(s2, s3));
        }
        const float mn0 = fmaxf(m0, cmax0), mn1 = fmaxf(m1, cmax1);
        float sum0 = 0.0f, sum1 = 0.0f;
#pragma unroll
        for (int nf = 0; nf < 16; ++nf) {
            sum0 += __expf(acc[nf * 4 + 0] - mn0) + __expf(acc[nf * 4 + 1] - mn0);
            sum1 += __expf(acc[nf * 4 + 2] - mn1) + __expf(acc[nf * 4 + 3] - mn1);
        }
        l0s = l0s * __expf(m0 - mn0) + sum0;  m0 = mn0;
        l1s = l1s * __expf(m1 - mn1) + sum1;  m1 = mn1;
    }

    // ---- cross-lane (quad) combine: lanes 4g..4g+3 share a row ----
#pragma unroll
    for (int off = 1; off <= 2; off <<= 1) {
        float mo0 = __shfl_xor_sync(0xFFFFFFFFu, m0, off);
        float lo0 = __shfl_xor_sync(0xFFFFFFFFu, l0s, off);
        float mn = fmaxf(m0, mo0);
        l0s = l0s * __expf(m0 - mn) + lo0 * __expf(mo0 - mn);  m0 = mn;
        float mo1 = __shfl_xor_sync(0xFFFFFFFFu, m1, off);
        float lo1 = __shfl_xor_sync(0xFFFFFFFFu, l1s, off);
        mn = fmaxf(m1, mo1);
        l1s = l1s * __expf(m1 - mn) + lo1 * __expf(mo1 - mn);  m1 = mn;
    }
    if (tig == 0) {
        g_rowM[(size_t)z * Ss + r0] = m0;
        g_rowL[(size_t)z * Ss + r0] = l0s;
        g_rowM[(size_t)z * Ss + r0 + 8] = m1;
        g_rowL[(size_t)z * Ss + r0 + 8] = l1s;
    }
}

// ===========================================================================
// Kernel 2: normalize P (write final score) + out = P @ V
// grid (qt=16, z=BH), block 256 = 8 warps. Output tile 128 x 64.
// Loops 16 k-chunks of 128. smem: Phi/Plo [128 x 128] fp16 (pitch 272B),
// Vhi [128 x 64] fp16 (pitch 144B, trans-loaded as B).
// ===========================================================================
#define S2_PHI 0
#define S2_PLO 34816
#define S2_VHI 69632
#define S2_SIZE 88064

__global__ __launch_bounds__(256, 2) void pv_kernel(
    const float4* __restrict__ V4, float* __restrict__ score,
    float* __restrict__ out)
{
    extern __shared__ char sm[];
    const uint32_t smb = smem_u32(sm);
    const int t = threadIdx.x, lane = t & 31, w = t >> 5;
    const int qt = blockIdx.x, z = blockIdx.y;

    const int row = t >> 1, ch = t & 1;
    const int grow = qt * 128 + row;
    const float mr   = g_rowM[(size_t)z * Ss + grow];
    const float invl = 1.0f / g_rowL[(size_t)z * Ss + grow];
    float* srow = score + (size_t)z * Ss * Ss + (size_t)grow * Ss + ch * 64;

    float acc[32];
#pragma unroll
    for (int i = 0; i < 32; ++i) acc[i] = 0.0f;

    for (int kc = 0; kc < 16; ++kc) {
        __syncthreads();
        // ---- P chunk: p = exp(s-m)/l, write back (final score), split fp16 ----
        {
            float4* sp = reinterpret_cast<float4*>(srow + kc * 128);
            char* dh = sm + S2_PHI + row * 272 + ch * 128;
            char* dl = sm + S2_PLO + row * 272 + ch * 128;
#pragma unroll
            for (int c = 0; c < 8; ++c) {
                float4 a = sp[2 * c], bv = sp[2 * c + 1];
                a.x = __expf(a.x - mr) * invl;  a.y = __expf(a.y - mr) * invl;
                a.z = __expf(a.z - mr) * invl;  a.w = __expf(a.w - mr) * invl;
                bv.x = __expf(bv.x - mr) * invl; bv.y = __expf(bv.y - mr) * invl;
                bv.z = __expf(bv.z - mr) * invl; bv.w = __expf(bv.w - mr) * invl;
                sp[2 * c] = a;  sp[2 * c + 1] = bv;
                uint32_t l0, l1, l2, l3;
                uint4 hh;
                hh.x = pack_hilo(a.x, a.y, l0);
                hh.y = pack_hilo(a.z, a.w, l1);
                hh.z = pack_hilo(bv.x, bv.y, l2);
                hh.w = pack_hilo(bv.z, bv.w, l3);
                *reinterpret_cast<uint4*>(dh + c * 16) = hh;
                *reinterpret_cast<uint4*>(dl + c * 16) = make_uint4(l0, l1, l2, l3);
            }
        }
        // ---- V chunk [128 k x 64 d] -> fp16 hi ----
        {
            const float4* g = V4 + ((size_t)z * Ss + (size_t)kc * 128 + row) * 16 + ch * 8;
            char* d = sm + S2_VHI + row * 144 + ch * 64;
#pragma unroll
            for (int c = 0; c < 4; ++c) {
                float4 a = g[2 * c], bv = g[2 * c + 1];
                uint4 hh;
                hh.x = pack_h(a.x, a.y);  hh.y = pack_h(a.z, a.w);
                hh.z = pack_h(bv.x, bv.y); hh.w = pack_h(bv.z, bv.w);
                *reinterpret_cast<uint4*>(d + c * 16) = hh;
            }
        }
        __syncthreads();

        // ---- MMA: [16 x 64] per warp, K-dim 128 (8 steps), A = Phi+Plo ----
#pragma unroll
        for (int ks = 0; ks < 8; ++ks) {
            const uint32_t aoff = (uint32_t)((w * 16 + (lane & 15)) * 272 +
                                             ks * 32 + (lane >> 4) * 16);
            uint32_t ah0, ah1, ah2, ah3, al0, al1, al2, al3;
            ldsm_x4(smb + S2_PHI + aoff, ah0, ah1, ah2, ah3);
            ldsm_x4(smb + S2_PLO + aoff, al0, al1, al2, al3);
#pragma unroll
            for (int nf2 = 0; nf2 < 4; ++nf2) {
                const int n0 = nf2 * 16;
                const uint32_t baddr = smb + S2_VHI +
                    (uint32_t)((ks * 16 + ((lane >> 3) & 1) * 8 + (lane & 7)) * 144 +
                               (n0 + (lane >> 4) * 8) * 2);
                uint32_t b0, b1, b2, b3;
                ldsm_x4_t(baddr, b0, b1, b2, b3);
                mma16816(acc + nf2 * 8,     ah0, ah1, ah2, ah3, b0, b1);
                mma16816(acc + nf2 * 8,     al0, al1, al2, al3, b0, b1);
                mma16816(acc + nf2 * 8 + 4, ah0, ah1, ah2, ah3, b2, b3);
                mma16816(acc + nf2 * 8 + 4, al0, al1, al2, al3, b2, b3);
            }
        }
    }

    // ---- epilogue: write out [128 x 64] ----
    const int tig = lane & 3;
    const int r0 = qt * 128 + w * 16 + (lane >> 2);
    float* o0 = out + ((size_t)z * Ss + r0) * Dd;
    float* o1 = o0 + 8 * Dd;
#pragma unroll
    for (int nf = 0; nf < 8; ++nf) {
        const int c = nf * 8 + tig * 2;
        float2 w0; w0.x = acc[nf * 4 + 0]; w0.y = acc[nf * 4 + 1];
        float2 w1; w1.x = acc[nf * 4 + 2]; w1.y = acc[nf * 4 + 3];
        *reinterpret_cast<float2*>(o0 + c) = w0;
        *reinterpret_cast<float2*>(o1 + c) = w1;
    }
}

// ===========================================================================
extern "C" void kernel_launch(void* const* d_in, const int* in_sizes, int n_in,
                              void* d_out, int out_size)
{
    const float* q    = (const float*)d_in[0];
    const float* k    = (const float*)d_in[1];
    const float* v    = (const float*)d_in[2];
    const int*   mask = (const int*)d_in[3];

    float* out   = (float*)d_out;
    float* score = out + OUT_ELEMS;   // tuple output: (output, score) concatenated

    cudaFuncSetAttribute(scores_kernel, cudaFuncAttributeMaxDynamicSharedMemorySize, S1_SIZE);
    cudaFuncSetAttribute(pv_kernel,     cudaFuncAttributeMaxDynamicSharedMemorySize, S2_SIZE);

    // K1: raw masked scores + row stats (z fast -> heads of same batch share mask in L2)
    scores_kernel<<<dim3(BH, 16), 256, S1_SIZE>>>(
        (const float4*)q, (const float4*)k, mask, score);

    // K2: normalize P (final score output) + P@V (qt fast -> blocks share V in L2)
    pv_kernel<<<dim3(16, BH), 256, S2_SIZE>>>(
        (const float4*)v, score, out);
}

// round 8
// speedup vs baseline: 2.9045x; 1.6795x over previous
#include <cuda_runtime.h>
#include <cuda_fp16.h>
#include <cstdint>
#include <math.h>

// Problem constants: B=4, H=16, S=2048, D=64
#define Bb 4
#define Hh 16
#define Ss 2048
#define Dd 64
#define BH (Bb*Hh)
#define SCALE 0.125f

static const long long OUT_ELEMS = (long long)Bb * Hh * Ss * Dd;   // 8,388,608

// ---------------------------------------------------------------------------
// smem layout (bytes). Q region [0, 36864) is reused as bitmask+stats after
// Q fragments are extracted into registers.
// ---------------------------------------------------------------------------
#define SM_QHI   0
#define SM_QLO   18432
#define SM_MASK  0          // 32 KB bitmask: word index kt*256 + tid
#define SM_STATM 32768      // float m[128]
#define SM_STATI 33280      // float invl[128]
#define SM_K     36864      // 2 buffers x 9216 (64 rows x 144B pitch)
#define SM_V     55296      // 2 buffers x 9216
#define SM_SIZE  73728

// ===========================================================================
// helpers
// ===========================================================================
__device__ __forceinline__ uint32_t smem_u32(const void* p) {
    uint32_t a;
    asm("{ .reg .u64 t; cvta.to.shared.u64 t, %1; cvt.u32.u64 %0, t; }"
        : "=r"(a) : "l"(p));
    return a;
}

__device__ __forceinline__ void ldsm_x4(uint32_t addr, uint32_t& r0, uint32_t& r1,
                                        uint32_t& r2, uint32_t& r3) {
    asm volatile("ldmatrix.sync.aligned.m8n8.x4.shared.b16 {%0,%1,%2,%3}, [%4];"
                 : "=r"(r0), "=r"(r1), "=r"(r2), "=r"(r3) : "r"(addr));
}

__device__ __forceinline__ void ldsm_x4_t(uint32_t addr, uint32_t& r0, uint32_t& r1,
                                          uint32_t& r2, uint32_t& r3) {
    asm volatile("ldmatrix.sync.aligned.m8n8.x4.trans.shared.b16 {%0,%1,%2,%3}, [%4];"
                 : "=r"(r0), "=r"(r1), "=r"(r2), "=r"(r3) : "r"(addr));
}

__device__ __forceinline__ void mma16816(float* c, uint32_t a0, uint32_t a1,
                                         uint32_t a2, uint32_t a3,
                                         uint32_t b0, uint32_t b1) {
    asm volatile("mma.sync.aligned.m16n8k16.row.col.f32.f16.f16.f32 "
                 "{%0,%1,%2,%3}, {%4,%5,%6,%7}, {%8,%9}, {%0,%1,%2,%3};"
                 : "+f"(c[0]), "+f"(c[1]), "+f"(c[2]), "+f"(c[3])
                 : "r"(a0), "r"(a1), "r"(a2), "r"(a3), "r"(b0), "r"(b1));
}

__device__ __forceinline__ uint32_t pack_hilo(float x, float y, uint32_t& lo) {
    __half hx = __float2half_rn(x), hy = __float2half_rn(y);
    float rx = x - __half2float(hx);
    float ry = y - __half2float(hy);
    lo = (uint32_t)__half_as_ushort(__float2half_rn(rx)) |
         ((uint32_t)__half_as_ushort(__float2half_rn(ry)) << 16);
    return (uint32_t)__half_as_ushort(hx) | ((uint32_t)__half_as_ushort(hy) << 16);
}
__device__ __forceinline__ uint32_t pack_h(float x, float y) {
    return (uint32_t)__half_as_ushort(__float2half_rn(x)) |
           ((uint32_t)__half_as_ushort(__float2half_rn(y)) << 16);
}

// Load a [64 x 64] fp32 tile (row-major, 64-elem rows) -> fp16 smem, pitch 144B.
__device__ __forceinline__ void load_tile64(const float4* __restrict__ gbase,
                                            char* dst, int t) {
    const int row = t >> 2, seg = t & 3;
    const float4* g = gbase + row * 16 + seg * 4;
    float4 f0 = g[0], f1 = g[1], f2 = g[2], f3 = g[3];
    uint4 u0, u1;
    u0.x = pack_h(f0.x, f0.y); u0.y = pack_h(f0.z, f0.w);
    u0.z = pack_h(f1.x, f1.y); u0.w = pack_h(f1.z, f1.w);
    u1.x = pack_h(f2.x, f2.y); u1.y = pack_h(f2.z, f2.w);
    u1.z = pack_h(f3.x, f3.y); u1.w = pack_h(f3.z, f3.w);
    char* d = dst + row * 144 + seg * 32;
    *reinterpret_cast<uint4*>(d)      = u0;
    *reinterpret_cast<uint4*>(d + 16) = u1;
}

// ===========================================================================
// Fused attention: one block = (z, 128 q-rows). Two passes over 32 k-tiles
// of 64 columns each. Pass 1: stats only (+mask bit cache). Pass 2: recompute
// scores, normalize+write, and P@V via register fragment reuse.
// ===========================================================================
__global__ __launch_bounds__(256, 2) void attn_kernel(
    const float4* __restrict__ Q4, const float4* __restrict__ K4,
    const float4* __restrict__ V4, const int* __restrict__ mask,
    float* __restrict__ score, float* __restrict__ out)
{
    extern __shared__ char sm[];
    const uint32_t smb = smem_u32(sm);
    const int t = threadIdx.x, lane = t & 31, w = t >> 5, tig = lane & 3;
    const int z = blockIdx.x, qt = blockIdx.y, b = z >> 4;

    // ---- load Q tile [128 x 64] fp32 -> fp16 hi/lo smem ----
    {
        const int row = t >> 1, ch = t & 1;
        const float4* g = Q4 + ((size_t)z * Ss + (size_t)qt * 128 + row) * 16 + ch * 8;
        char* dh = sm + SM_QHI + row * 144 + ch * 64;
        char* dl = sm + SM_QLO + row * 144 + ch * 64;
#pragma unroll
        for (int c = 0; c < 4; ++c) {
            float4 a = g[2 * c], bq = g[2 * c + 1];
            uint32_t l0, l1, l2, l3;
            uint4 hh;
            hh.x = pack_hilo(a.x, a.y, l0);
            hh.y = pack_hilo(a.z, a.w, l1);
            hh.z = pack_hilo(bq.x, bq.y, l2);
            hh.w = pack_hilo(bq.z, bq.w, l3);
            *reinterpret_cast<uint4*>(dh + c * 16) = hh;
            *reinterpret_cast<uint4*>(dl + c * 16) = make_uint4(l0, l1, l2, l3);
        }
    }
    __syncthreads();

    // ---- extract Q fragments into registers (persist whole kernel) ----
    uint32_t qh[4][4], ql[4][4];
#pragma unroll
    for (int ks = 0; ks < 4; ++ks) {
        uint32_t aoff = (uint32_t)((w * 16 + (lane & 15)) * 144 + ks * 32 + (lane >> 4) * 16);
        ldsm_x4(smb + SM_QHI + aoff, qh[ks][0], qh[ks][1], qh[ks][2], qh[ks][3]);
        ldsm_x4(smb + SM_QLO + aoff, ql[ks][0], ql[ks][1], ql[ks][2], ql[ks][3]);
    }
    __syncthreads();   // Q smem region now free -> reused for bitmask + stats

    uint32_t* maskSm = reinterpret_cast<uint32_t*>(sm + SM_MASK);
    float* mSt = reinterpret_cast<float*>(sm + SM_STATM);
    float* iSt = reinterpret_cast<float*>(sm + SM_STATI);

    const int lrow = w * 16 + (lane >> 2);          // local row (quad-owned)
    const int grow = qt * 128 + lrow;               // global q-row
    const int* mrow0 = mask + (size_t)b * Ss * Ss + (size_t)grow * Ss;
    const int* mrow1 = mrow0 + 8 * Ss;
    float* srow0 = score + (size_t)z * Ss * Ss + (size_t)grow * Ss;
    float* srow1 = srow0 + 8 * Ss;

    float m0 = -INFINITY, m1 = -INFINITY, l0s = 0.0f, l1s = 0.0f;

    // =================== PASS 1: stats + bitmask cache ===================
    load_tile64(K4 + (size_t)z * Ss * 16, sm + SM_K, t);
    for (int kt = 0; kt < 32; ++kt) {
        __syncthreads();
        if (kt < 31)
            load_tile64(K4 + ((size_t)z * Ss + (size_t)(kt + 1) * 64) * 16,
                        sm + SM_K + ((kt + 1) & 1) * 9216, t);

        // mask -> 32 bits (2 rows x 16 cols owned by this lane in this tile)
        uint32_t bits = 0;
        {
            const int cb = kt * 64 + tig * 2;
#pragma unroll
            for (int j = 0; j < 8; ++j) {
                int2 a = *reinterpret_cast<const int2*>(mrow0 + cb + j * 8);
                int2 c = *reinterpret_cast<const int2*>(mrow1 + cb + j * 8);
                bits |= (a.x != 0 ? 1u : 0u) << (4 * j)
                      | (a.y != 0 ? 1u : 0u) << (4 * j + 1)
                      | (c.x != 0 ? 1u : 0u) << (4 * j + 2)
                      | (c.y != 0 ? 1u : 0u) << (4 * j + 3);
            }
        }
        maskSm[kt * 256 + t] = bits;

        float acc[32];
#pragma unroll
        for (int i = 0; i < 32; ++i) acc[i] = 0.0f;
        const uint32_t kb = smb + SM_K + (kt & 1) * 9216;
#pragma unroll
        for (int ks = 0; ks < 4; ++ks) {
#pragma unroll
            for (int n16 = 0; n16 < 4; ++n16) {
                uint32_t baddr = kb + (uint32_t)((n16 * 16 + (lane >> 4) * 8 + (lane & 7)) * 144
                                  + ks * 32 + ((lane >> 3) & 1) * 16);
                uint32_t b0, b1, b2, b3;
                ldsm_x4(baddr, b0, b1, b2, b3);
                mma16816(acc + n16 * 8,     qh[ks][0], qh[ks][1], qh[ks][2], qh[ks][3], b0, b1);
                mma16816(acc + n16 * 8,     ql[ks][0], ql[ks][1], ql[ks][2], ql[ks][3], b0, b1);
                mma16816(acc + n16 * 8 + 4, qh[ks][0], qh[ks][1], qh[ks][2], qh[ks][3], b2, b3);
                mma16816(acc + n16 * 8 + 4, ql[ks][0], ql[ks][1], ql[ks][2], ql[ks][3], b2, b3);
            }
        }

        // masked scores -> online (m, l)
        float cmax0 = -INFINITY, cmax1 = -INFINITY;
#pragma unroll
        for (int j = 0; j < 8; ++j) {
            float s0 = ((bits >> (4 * j))     & 1) ? acc[4 * j + 0] * SCALE : 1e-12f;
            float s1 = ((bits >> (4 * j + 1)) & 1) ? acc[4 * j + 1] * SCALE : 1e-12f;
            float s2 = ((bits >> (4 * j + 2)) & 1) ? acc[4 * j + 2] * SCALE : 1e-12f;
            float s3 = ((bits >> (4 * j + 3)) & 1) ? acc[4 * j + 3] * SCALE : 1e-12f;
            acc[4 * j + 0] = s0; acc[4 * j + 1] = s1;
            acc[4 * j + 2] = s2; acc[4 * j + 3] = s3;
            cmax0 = fmaxf(cmax0, fmaxf(s0, s1));
            cmax1 = fmaxf(cmax1, fmaxf(s2, s3));
        }
        float mn0 = fmaxf(m0, cmax0), mn1 = fmaxf(m1, cmax1);
        float sum0 = 0.0f, sum1 = 0.0f;
#pragma unroll
        for (int j = 0; j < 8; ++j) {
            sum0 += __expf(acc[4 * j + 0] - mn0) + __expf(acc[4 * j + 1] - mn0);
            sum1 += __expf(acc[4 * j + 2] - mn1) + __expf(acc[4 * j + 3] - mn1);
        }
        l0s = l0s * __expf(m0 - mn0) + sum0;  m0 = mn0;
        l1s = l1s * __expf(m1 - mn1) + sum1;  m1 = mn1;
    }

    // quad combine (lanes 4g..4g+3 share rows)
#pragma unroll
    for (int off = 1; off <= 2; off <<= 1) {
        float mo = __shfl_xor_sync(0xFFFFFFFFu, m0, off);
        float lo = __shfl_xor_sync(0xFFFFFFFFu, l0s, off);
        float mn = fmaxf(m0, mo);
        l0s = l0s * __expf(m0 - mn) + lo * __expf(mo - mn);  m0 = mn;
        mo = __shfl_xor_sync(0xFFFFFFFFu, m1, off);
        lo = __shfl_xor_sync(0xFFFFFFFFu, l1s, off);
        mn = fmaxf(m1, mo);
        l1s = l1s * __expf(m1 - mn) + lo * __expf(mo - mn);  m1 = mn;
    }
    if (tig == 0) {
        mSt[lrow] = m0;      iSt[lrow] = 1.0f / l0s;
        mSt[lrow + 8] = m1;  iSt[lrow + 8] = 1.0f / l1s;
    }
    __syncthreads();
    const float M0 = mSt[lrow],     I0 = iSt[lrow];
    const float M1 = mSt[lrow + 8], I1 = iSt[lrow + 8];

    // =================== PASS 2: recompute + normalize + PV ===================
    float acco[32];
#pragma unroll
    for (int i = 0; i < 32; ++i) acco[i] = 0.0f;

    load_tile64(K4 + (size_t)z * Ss * 16, sm + SM_K, t);
    load_tile64(V4 + (size_t)z * Ss * 16, sm + SM_V, t);

    for (int kt = 0; kt < 32; ++kt) {
        __syncthreads();
        if (kt < 31) {
            load_tile64(K4 + ((size_t)z * Ss + (size_t)(kt + 1) * 64) * 16,
                        sm + SM_K + ((kt + 1) & 1) * 9216, t);
            load_tile64(V4 + ((size_t)z * Ss + (size_t)(kt + 1) * 64) * 16,
                        sm + SM_V + ((kt + 1) & 1) * 9216, t);
        }
        const uint32_t bits = maskSm[kt * 256 + t];

        float acc[32];
#pragma unroll
        for (int i = 0; i < 32; ++i) acc[i] = 0.0f;
        const uint32_t kb = smb + SM_K + (kt & 1) * 9216;
#pragma unroll
        for (int ks = 0; ks < 4; ++ks) {
#pragma unroll
            for (int n16 = 0; n16 < 4; ++n16) {
                uint32_t baddr = kb + (uint32_t)((n16 * 16 + (lane >> 4) * 8 + (lane & 7)) * 144
                                  + ks * 32 + ((lane >> 3) & 1) * 16);
                uint32_t b0, b1, b2, b3;
                ldsm_x4(baddr, b0, b1, b2, b3);
                mma16816(acc + n16 * 8,     qh[ks][0], qh[ks][1], qh[ks][2], qh[ks][3], b0, b1);
                mma16816(acc + n16 * 8,     ql[ks][0], ql[ks][1], ql[ks][2], ql[ks][3], b0, b1);
                mma16816(acc + n16 * 8 + 4, qh[ks][0], qh[ks][1], qh[ks][2], qh[ks][3], b2, b3);
                mma16816(acc + n16 * 8 + 4, ql[ks][0], ql[ks][1], ql[ks][2], ql[ks][3], b2, b3);
            }
        }

        const uint32_t vb = smb + SM_V + (kt & 1) * 9216;
#pragma unroll
        for (int kk = 0; kk < 4; ++kk) {
            const int j0 = 2 * kk, j1 = 2 * kk + 1;
            float p[8];
            {
                float s0 = ((bits >> (4 * j0))     & 1) ? acc[4 * j0 + 0] * SCALE : 1e-12f;
                float s1 = ((bits >> (4 * j0 + 1)) & 1) ? acc[4 * j0 + 1] * SCALE : 1e-12f;
                float s2 = ((bits >> (4 * j0 + 2)) & 1) ? acc[4 * j0 + 2] * SCALE : 1e-12f;
                float s3 = ((bits >> (4 * j0 + 3)) & 1) ? acc[4 * j0 + 3] * SCALE : 1e-12f;
                p[0] = __expf(s0 - M0) * I0;  p[1] = __expf(s1 - M0) * I0;
                p[2] = __expf(s2 - M1) * I1;  p[3] = __expf(s3 - M1) * I1;
                s0 = ((bits >> (4 * j1))     & 1) ? acc[4 * j1 + 0] * SCALE : 1e-12f;
                s1 = ((bits >> (4 * j1 + 1)) & 1) ? acc[4 * j1 + 1] * SCALE : 1e-12f;
                s2 = ((bits >> (4 * j1 + 2)) & 1) ? acc[4 * j1 + 2] * SCALE : 1e-12f;
                s3 = ((bits >> (4 * j1 + 3)) & 1) ? acc[4 * j1 + 3] * SCALE : 1e-12f;
                p[4] = __expf(s0 - M0) * I0;  p[5] = __expf(s1 - M0) * I0;
                p[6] = __expf(s2 - M1) * I1;  p[7] = __expf(s3 - M1) * I1;
            }
            // write normalized score (final output)
            {
                const int c0 = kt * 64 + j0 * 8 + tig * 2;
                const int c1 = kt * 64 + j1 * 8 + tig * 2;
                float2 w0; w0.x = p[0]; w0.y = p[1];
                float2 w1; w1.x = p[2]; w1.y = p[3];
                float2 w2; w2.x = p[4]; w2.y = p[5];
                float2 w3; w3.x = p[6]; w3.y = p[7];
                *reinterpret_cast<float2*>(srow0 + c0) = w0;
                *reinterpret_cast<float2*>(srow1 + c0) = w1;
                *reinterpret_cast<float2*>(srow0 + c1) = w2;
                *reinterpret_cast<float2*>(srow1 + c1) = w3;
            }
            // A-fragments for PV (D-frag layout == A-frag layout), hi/lo split
            uint32_t ah0, ah1, ah2, ah3, al0, al1, al2, al3;
            ah0 = pack_hilo(p[0], p[1], al0);
            ah1 = pack_hilo(p[2], p[3], al1);
            ah2 = pack_hilo(p[4], p[5], al2);
            ah3 = pack_hilo(p[6], p[7], al3);
#pragma unroll
            for (int d16 = 0; d16 < 4; ++d16) {
                uint32_t baddr = vb + (uint32_t)((kk * 16 + ((lane >> 3) & 1) * 8 + (lane & 7)) * 144
                                  + d16 * 32 + (lane >> 4) * 16);
                uint32_t b0, b1, b2, b3;
                ldsm_x4_t(baddr, b0, b1, b2, b3);
                mma16816(acco + d16 * 8,     ah0, ah1, ah2, ah3, b0, b1);
                mma16816(acco + d16 * 8,     al0, al1, al2, al3, b0, b1);
                mma16816(acco + d16 * 8 + 4, ah0, ah1, ah2, ah3, b2, b3);
                mma16816(acco + d16 * 8 + 4, al0, al1, al2, al3, b2, b3);
            }
        }
    }

    // ---- out epilogue [128 x 64] ----
    float* o0 = out + ((size_t)z * Ss + grow) * Dd;
    float* o1 = o0 + 8 * Dd;
#pragma unroll
    for (int nf = 0; nf < 8; ++nf) {
        const int c = nf * 8 + tig * 2;
        float2 w0; w0.x = acco[nf * 4 + 0]; w0.y = acco[nf * 4 + 1];
        float2 w1; w1.x = acco[nf * 4 + 2]; w1.y = acco[nf * 4 + 3];
        *reinterpret_cast<float2*>(o0 + c) = w0;
        *reinterpret_cast<float2*>(o1 + c) = w1;
    }
}

// ===========================================================================
extern "C" void kernel_launch(void* const* d_in, const int* in_sizes, int n_in,
                              void* d_out, int out_size)
{
    const float* q    = (const float*)d_in[0];
    const float* k    = (const float*)d_in[1];
    const float* v    = (const float*)d_in[2];
    const int*   mask = (const int*)d_in[3];

    float* out   = (float*)d_out;
    float* score = out + OUT_ELEMS;   // tuple output: (output, score) concatenated

    cudaFuncSetAttribute(attn_kernel, cudaFuncAttributeMaxDynamicSharedMemorySize, SM_SIZE);

    // z fast -> concurrent blocks: all heads, same qt => mask rows + K/V shared in L2
    attn_kernel<<<dim3(BH, 16), 256, SM_SIZE>>>(
        (const float4*)q, (const float4*)k, (const float4*)v, mask, score, out);
}